// round 4
// baseline (speedup 1.0000x reference)
#include <cuda_runtime.h>
#include <cuda_bf16.h>
#include <stdint.h>

// Problem constants (fixed by setup_inputs)
#define BB   32
#define SS   8192
#define CC   256
#define KK   64
#define TILE 16            // columns per block
#define CAP  160           // candidate slots per column (mean~117, sd~10.7)
#define RMAX 5             // CAP/32

// Threshold 2.1875: P(X>t)=0.0143 -> ~117 candidates/column.
#define THRESH 2.1875f

// Fallback plumbing (device globals — allocation-free)
__device__ unsigned int g_fb_n;
__device__ int          g_fb_list[BB * CC];

__device__ __forceinline__ unsigned int fkey(float f) {
    unsigned int u = __float_as_uint(f);
    return (u & 0x80000000u) ? ~u : (u | 0x80000000u);
}

// ---------------------------------------------------------------------------
// Fused kernel: stream 16 columns -> smem candidates -> per-warp top-K select.
// ---------------------------------------------------------------------------
__global__ void __launch_bounds__(512) fused_kernel(const float* __restrict__ x,
                                                    float* __restrict__ out) {
    __shared__ unsigned long long sbuf[TILE * CAP];   // 20 KB
    __shared__ int scnt[TILE];

    const int tid = threadIdx.x;
    const int ct  = blockIdx.x & 15;        // column tile (16 tiles of 16)
    const int b   = blockIdx.x >> 4;        // batch

    if (tid < TILE) scnt[tid] = 0;
    __syncthreads();

    // ---- stream phase: coalesced float4 over all rows of this tile ----
    const int q  = tid & 3;                 // float4 within the 16-col chunk
    const int sr = tid >> 2;                // 0..127 (row within iter group)
    const float4* __restrict__ x4 = reinterpret_cast<const float4*>(x);
    const size_t rowbase = (size_t)b * SS;  // row index base

#pragma unroll 4
    for (int it = 0; it < 64; it++) {
        const int s = it * 128 + sr;
        float4 v = __ldcs(&x4[(rowbase + s) * (CC / 4) + ct * 4 + q]);
        float m = fmaxf(fmaxf(v.x, v.y), fmaxf(v.z, v.w));
        if (m >= THRESH) {
            float vals[4] = {v.x, v.y, v.z, v.w};
#pragma unroll
            for (int l = 0; l < 4; l++) {
                if (vals[l] >= THRESH) {
                    const int cl = q * 4 + l;
                    int pos = atomicAdd(&scnt[cl], 1);
                    if (pos < CAP) {
                        // positive floats: monotone key = bits | signbit
                        unsigned int key = __float_as_uint(vals[l]) | 0x80000000u;
                        sbuf[cl * CAP + pos] =
                            ((unsigned long long)key << 32) | (unsigned int)s;
                    }
                }
            }
        }
    }
    __syncthreads();

    // ---- select phase: warp w owns column w of the tile ----
    const int w    = tid >> 5;
    const int lane = tid & 31;
    const int n    = scnt[w];
    const int cg   = ct * TILE + w;         // global column within C

    if (n >= KK && n <= CAP) {
        const int nr = (n + 31) >> 5;       // valid 32-rounds (<= RMAX)

        unsigned long long c[RMAX];
        int rank[RMAX];
#pragma unroll
        for (int r = 0; r < RMAX; r++) {
            int idx = r * 32 + lane;
            c[r] = (r < nr && idx < n) ? sbuf[w * CAP + idx] : 0ull;
            rank[r] = 0;
        }

        // rank_i = #{ j : comp_j > comp_i }  (composites distinct)
#pragma unroll
        for (int r2 = 0; r2 < RMAX; r2++) {
            if (r2 < nr) {
                for (int src = 0; src < 32; src++) {
                    unsigned long long cj =
                        __shfl_sync(0xffffffffu, c[r2], src);
#pragma unroll
                    for (int r = 0; r < RMAX; r++) rank[r] += (cj > c[r]);
                }
            }
        }

        // packed: bit31 = selected, low bits = s (< 8192)
        unsigned int pk[RMAX];
        int pos[RMAX];
#pragma unroll
        for (int r = 0; r < RMAX; r++) {
            bool sel = (rank[r] < KK) && (r * 32 + lane < n) && (r < nr);
            pk[r] = (unsigned int)c[r] | (sel ? 0x80000000u : 0u);
            pos[r] = 0;
        }

        // pos_i = #{ selected j : s_j < s_i }
        // trick: (pj + 0x80000000) < s_i  <=>  sel_j && s_j < s_i
#pragma unroll
        for (int r2 = 0; r2 < RMAX; r2++) {
            if (r2 < nr) {
                for (int src = 0; src < 32; src++) {
                    unsigned int pj = __shfl_sync(0xffffffffu, pk[r2], src);
#pragma unroll
                    for (int r = 0; r < RMAX; r++)
                        pos[r] += ((pj + 0x80000000u) < (unsigned int)c[r]);
                }
            }
        }

#pragma unroll
        for (int r = 0; r < RMAX; r++) {
            if (pk[r] & 0x80000000u) {
                unsigned int key = (unsigned int)(c[r] >> 32);
                out[((size_t)b * KK + pos[r]) * CC + cg] =
                    __uint_as_float(key & 0x7FFFFFFFu);
            }
        }
    } else {
        if (lane == 0) {
            unsigned int i = atomicAdd(&g_fb_n, 1u);
            g_fb_list[i] = b * CC + cg;
        }
    }
}

// ---------------------------------------------------------------------------
// Exact fallback: block per flagged column; column cached in smem, then
// 64-pass bitwise select on the (key,s) composite + ordered scatter.
// ---------------------------------------------------------------------------
__global__ void __launch_bounds__(256) fallback_kernel(const float* __restrict__ x,
                                                       float* __restrict__ out) {
    __shared__ float scol[SS];              // 32 KB
    __shared__ int scnt[256];
    const int tid = threadIdx.x;
    const unsigned int nfb = g_fb_n;

    for (unsigned int i = blockIdx.x; i < nfb; i += gridDim.x) {
        const int col = g_fb_list[i];
        const int b = col >> 8;
        const int c = col & (CC - 1);

        for (int s = tid; s < SS; s += 256)
            scol[s] = x[((size_t)b * SS + s) * CC + c];
        __syncthreads();

        // V = K-th largest 64-bit composite, built bit by bit.
        unsigned long long V = 0;
        for (int bit = 63; bit >= 0; bit--) {
            unsigned long long cand = V | (1ull << bit);
            int local = 0;
            for (int s = tid; s < SS; s += 256) {
                unsigned long long comp =
                    ((unsigned long long)fkey(scol[s]) << 32) | (unsigned int)s;
                local += (comp >= cand);
            }
            scnt[tid] = local;
            __syncthreads();
            for (int st = 128; st > 0; st >>= 1) {
                if (tid < st) scnt[tid] += scnt[tid + st];
                __syncthreads();
            }
            int cnt = scnt[0];
            __syncthreads();
            if (cnt >= KK) V = cand;
        }

        // Ordered write: thread t owns contiguous s-range, exclusive scan.
        const int per = SS / 256;           // 32
        int lcnt = 0;
        for (int k2 = 0; k2 < per; k2++) {
            int s = tid * per + k2;
            unsigned long long comp =
                ((unsigned long long)fkey(scol[s]) << 32) | (unsigned int)s;
            lcnt += (comp >= V);
        }
        scnt[tid] = lcnt;
        __syncthreads();
        for (int off = 1; off < 256; off <<= 1) {
            int vv = scnt[tid];
            int ww = (tid >= off) ? scnt[tid - off] : 0;
            __syncthreads();
            scnt[tid] = vv + ww;
            __syncthreads();
        }
        int base = scnt[tid] - lcnt;
        for (int k2 = 0; k2 < per; k2++) {
            int s = tid * per + k2;
            unsigned long long comp =
                ((unsigned long long)fkey(scol[s]) << 32) | (unsigned int)s;
            if (comp >= V) {
                if (base < KK)
                    out[((size_t)b * KK + base) * CC + c] = scol[s];
                base++;
            }
        }
        __syncthreads();                    // before scol reuse
    }
}

extern "C" void kernel_launch(void* const* d_in, const int* in_sizes, int n_in,
                              void* d_out, int out_size) {
    const float* x = (const float*)d_in[0];
    float* out = (float*)d_out;

    void* fb_ptr = nullptr;
    cudaGetSymbolAddress(&fb_ptr, g_fb_n);
    cudaMemsetAsync(fb_ptr, 0, sizeof(unsigned int));

    fused_kernel<<<BB * (CC / TILE), 512>>>(x, out);   // 512 blocks
    fallback_kernel<<<32, 256>>>(x, out);
}

// round 6
// speedup vs baseline: 2.5420x; 2.5420x over previous
#include <cuda_runtime.h>
#include <cuda_bf16.h>
#include <stdint.h>

// Problem constants (fixed by setup_inputs)
#define BB    32
#define SS    8192
#define CC    256
#define KK    64
#define NCOL  (BB * CC)      // 8192 columns
#define CH    8              // row chunks per column
#define CHROWS (SS / CH)     // 1024
#define CHCAP 48             // per-chunk candidate slots (mean 14.6, sd 3.8)
#define NSEL  256            // bitonic size (total candidates mean 117, sd 10.7)

// Threshold 2.1875: P(X>t)=0.0143 -> ~117 candidates/column.
#define THRESH 2.1875f

// Scratch (device globals — allocation-free per harness rules)
__device__ unsigned long long g_cand[(size_t)NCOL * CH * CHCAP];  // 25.2 MB
__device__ int                g_cnt[NCOL * CH];
__device__ unsigned int       g_fb_n;
__device__ int                g_fb_list[NCOL];

__device__ __forceinline__ unsigned int fkey(float f) {
    unsigned int u = __float_as_uint(f);
    return (u & 0x80000000u) ? ~u : (u | 0x80000000u);
}

// ---------------------------------------------------------------------------
// Stream kernel: grid = 32b x 16tile x 8chunk. Minimal registers, full
// occupancy, one coalesced pass over x. Candidates -> per-(col,chunk) global
// segments; slot index from a shared-memory counter (no global atomics).
// ---------------------------------------------------------------------------
__global__ void __launch_bounds__(256) stream_kernel(const float* __restrict__ x) {
    __shared__ int scnt[16];
    const int tid = threadIdx.x;
    const int bid = blockIdx.x;
    const int h   = bid & 7;
    const int ct  = (bid >> 3) & 15;
    const int b   = bid >> 7;

    if (tid < 16) scnt[tid] = 0;
    __syncthreads();

    const int q  = tid & 3;                 // float4 within the 64B tile row
    const int sr = tid >> 2;                // 0..63
    const float4* __restrict__ x4 = reinterpret_cast<const float4*>(x);
    const size_t base = (size_t)b * SS * (CC / 4) + ct * 4 + q;
    const int colbase = b * CC + ct * 16 + q * 4;

#pragma unroll 4
    for (int it = 0; it < 16; it++) {
        const int s = h * CHROWS + it * 64 + sr;
        float4 v = __ldcs(&x4[base + (size_t)s * (CC / 4)]);
        float m = fmaxf(fmaxf(v.x, v.y), fmaxf(v.z, v.w));
        if (m >= THRESH) {
            float vals[4] = {v.x, v.y, v.z, v.w};
#pragma unroll
            for (int l = 0; l < 4; l++) {
                if (vals[l] >= THRESH) {
                    const int cl = q * 4 + l;
                    int pos = atomicAdd(&scnt[cl], 1);
                    if (pos < CHCAP) {
                        unsigned int key = __float_as_uint(vals[l]) | 0x80000000u;
                        g_cand[((size_t)(colbase + l) * CH + h) * CHCAP + pos] =
                            ((unsigned long long)key << 32) | (unsigned int)s;
                    }
                }
            }
        }
    }
    __syncthreads();
    if (tid < 16)
        g_cnt[(b * CC + ct * 16 + tid) * CH + h] = scnt[tid];
}

// ---------------------------------------------------------------------------
// Select kernel: one warp per column. Compact chunk segments into smem,
// register bitonic sort of 256 u64 composites (8/lane), take top-64,
// bitonic re-sort by original index, write out.
// ---------------------------------------------------------------------------
__global__ void __launch_bounds__(256) select_kernel(float* __restrict__ out) {
    __shared__ unsigned long long sbuf[8][NSEL];    // 16 KB

    const int tid  = threadIdx.x;
    const int w    = tid >> 5;
    const int lane = tid & 31;
    const int col  = blockIdx.x * 8 + w;
    const int b    = col >> 8;
    const int c    = col & (CC - 1);

    // counts + exclusive scan over 8 chunks (lanes 0..7)
    int cnt = (lane < CH) ? g_cnt[col * CH + lane] : 0;
    unsigned int ovf = __ballot_sync(0xffffffffu, (lane < CH) && (cnt > CHCAP));
    int sc = cnt;
#pragma unroll
    for (int d = 1; d < 8; d <<= 1) {
        int t2 = __shfl_up_sync(0xffffffffu, sc, d);
        if (lane >= d) sc += t2;
    }
    const int n = __shfl_sync(0xffffffffu, sc, CH - 1);
    const int excl = sc - cnt;

    if (n >= KK && n <= NSEL && ovf == 0u) {
        // ---- compact segments into smem ----
#pragma unroll
        for (int h = 0; h < CH; h++) {
            int chn  = __shfl_sync(0xffffffffu, cnt, h);
            int bs   = __shfl_sync(0xffffffffu, excl, h);
            const unsigned long long* src = &g_cand[((size_t)col * CH + h) * CHCAP];
            for (int i = lane; i < chn; i += 32)
                sbuf[w][bs + i] = src[i];
        }
        __syncwarp();

        unsigned long long v[8];
#pragma unroll
        for (int r = 0; r < 8; r++) {
            int e = r * 32 + lane;
            v[r] = (e < n) ? sbuf[w][e] : 0ull;   // zeros sort to the bottom
        }

        // ---- bitonic ascending sort of 256 u64 (e = r*32 + lane) ----
#pragma unroll
        for (int k = 2; k <= NSEL; k <<= 1) {
#pragma unroll
            for (int j = k >> 1; j > 0; j >>= 1) {
                if (j < 32) {
#pragma unroll
                    for (int r = 0; r < 8; r++) {
                        const int e = r * 32 + lane;
                        unsigned long long pv =
                            __shfl_xor_sync(0xffffffffu, v[r], j);
                        bool keep_min = (((e & k) == 0) == ((lane & j) == 0));
                        v[r] = ((v[r] < pv) == keep_min) ? v[r] : pv;
                    }
                } else {
                    const int jr = j >> 5;
#pragma unroll
                    for (int r = 0; r < 8; r++) {
                        if ((r & jr) == 0) {
                            const int r2 = r | jr;
                            const int e = r * 32 + lane;
                            bool asc = ((e & k) == 0);
                            unsigned long long a = v[r], bb = v[r2];
                            if (asc ? (a > bb) : (a < bb)) { v[r] = bb; v[r2] = a; }
                        }
                    }
                }
            }
        }

        // top-64 are elements e in [192,256) -> registers v[6], v[7]
        // ---- bitonic ascending sort of 64 by low-32 bits (original s) ----
#pragma unroll
        for (int k = 2; k <= 64; k <<= 1) {
#pragma unroll
            for (int j = k >> 1; j > 0; j >>= 1) {
                if (j < 32) {
#pragma unroll
                    for (int r = 6; r < 8; r++) {
                        const int f = (r - 6) * 32 + lane;
                        unsigned long long pv =
                            __shfl_xor_sync(0xffffffffu, v[r], j);
                        bool keep_min = (((f & k) == 0) == ((lane & j) == 0));
                        bool mine_min = ((unsigned int)v[r] < (unsigned int)pv);
                        v[r] = (mine_min == keep_min) ? v[r] : pv;
                    }
                } else {  // j == 32 (k == 64): ascending merge across v6/v7
                    unsigned long long a = v[6], bb = v[7];
                    if ((unsigned int)a > (unsigned int)bb) { v[6] = bb; v[7] = a; }
                }
            }
        }

        // ---- write: element f -> out[b][f][c] ----
#pragma unroll
        for (int r = 6; r < 8; r++) {
            const int f = (r - 6) * 32 + lane;
            unsigned int key = (unsigned int)(v[r] >> 32);
            out[((size_t)b * KK + f) * CC + c] = __uint_as_float(key & 0x7FFFFFFFu);
        }
    } else {
        if (lane == 0) {
            unsigned int i = atomicAdd(&g_fb_n, 1u);
            g_fb_list[i] = col;
        }
    }
}

// ---------------------------------------------------------------------------
// Exact fallback (expected no-op): block per flagged column; smem-cached
// column, 64-pass bitwise select on (key,s) composite + ordered scatter.
// ---------------------------------------------------------------------------
__global__ void __launch_bounds__(256) fallback_kernel(const float* __restrict__ x,
                                                       float* __restrict__ out) {
    __shared__ float scol[SS];              // 32 KB
    __shared__ int scnt[256];
    const int tid = threadIdx.x;
    const unsigned int nfb = g_fb_n;

    for (unsigned int i = blockIdx.x; i < nfb; i += gridDim.x) {
        const int col = g_fb_list[i];
        const int b = col >> 8;
        const int c = col & (CC - 1);

        for (int s = tid; s < SS; s += 256)
            scol[s] = x[((size_t)b * SS + s) * CC + c];
        __syncthreads();

        unsigned long long V = 0;
        for (int bit = 63; bit >= 0; bit--) {
            unsigned long long cand = V | (1ull << bit);
            int local = 0;
            for (int s = tid; s < SS; s += 256) {
                unsigned long long comp =
                    ((unsigned long long)fkey(scol[s]) << 32) | (unsigned int)s;
                local += (comp >= cand);
            }
            scnt[tid] = local;
            __syncthreads();
            for (int st = 128; st > 0; st >>= 1) {
                if (tid < st) scnt[tid] += scnt[tid + st];
                __syncthreads();
            }
            int cntv = scnt[0];
            __syncthreads();
            if (cntv >= KK) V = cand;
        }

        const int per = SS / 256;
        int lcnt = 0;
        for (int k2 = 0; k2 < per; k2++) {
            int s = tid * per + k2;
            unsigned long long comp =
                ((unsigned long long)fkey(scol[s]) << 32) | (unsigned int)s;
            lcnt += (comp >= V);
        }
        scnt[tid] = lcnt;
        __syncthreads();
        for (int off = 1; off < 256; off <<= 1) {
            int vv = scnt[tid];
            int ww = (tid >= off) ? scnt[tid - off] : 0;
            __syncthreads();
            scnt[tid] = vv + ww;
            __syncthreads();
        }
        int base = scnt[tid] - lcnt;
        for (int k2 = 0; k2 < per; k2++) {
            int s = tid * per + k2;
            unsigned long long comp =
                ((unsigned long long)fkey(scol[s]) << 32) | (unsigned int)s;
            if (comp >= V) {
                if (base < KK)
                    out[((size_t)b * KK + base) * CC + c] = scol[s];
                base++;
            }
        }
        __syncthreads();
    }
}

extern "C" void kernel_launch(void* const* d_in, const int* in_sizes, int n_in,
                              void* d_out, int out_size) {
    const float* x = (const float*)d_in[0];
    float* out = (float*)d_out;

    void* fb_ptr = nullptr;
    cudaGetSymbolAddress(&fb_ptr, g_fb_n);
    cudaMemsetAsync(fb_ptr, 0, sizeof(unsigned int));

    stream_kernel<<<BB * 16 * CH, 256>>>(x);     // 4096 blocks
    select_kernel<<<NCOL / 8, 256>>>(out);       // 1024 blocks
    fallback_kernel<<<64, 256>>>(x, out);
}

// round 7
// speedup vs baseline: 3.0910x; 1.2160x over previous
#include <cuda_runtime.h>
#include <cuda_bf16.h>
#include <stdint.h>

// Problem constants (fixed by setup_inputs)
#define BB    32
#define SS    8192
#define CC    256
#define KK    64
#define NCOL  (BB * CC)      // 8192 columns
#define CH    8              // row chunks per column
#define CHROWS (SS / CH)     // 1024
#define CHCAP 48             // per-chunk candidate slots (mean 14.6, sd 3.8)
#define NSEL  256            // max bitonic size (candidates mean 117, sd 10.7)

// Threshold 2.1875: P(X>t)=0.0143 -> ~117 candidates/column.
#define THRESH 2.1875f

// Scratch (device globals — allocation-free per harness rules)
__device__ unsigned long long g_cand[(size_t)NCOL * CH * CHCAP];  // 25.2 MB
__device__ int                g_cnt[NCOL * CH];
__device__ unsigned int       g_fb_n;
__device__ int                g_fb_list[NCOL];

__device__ __forceinline__ unsigned int fkey(float f) {
    unsigned int u = __float_as_uint(f);
    return (u & 0x80000000u) ? ~u : (u | 0x80000000u);
}

// ---------------------------------------------------------------------------
// Stream kernel: grid = 32b x 16tile x 8chunk. One coalesced pass over x with
// EXPLICIT 4-deep load batching (front-issued LDGs -> MLP=4/thread) so the
// branchy filter never serializes the memory stream.
// ---------------------------------------------------------------------------
__global__ void __launch_bounds__(256) stream_kernel(const float* __restrict__ x) {
    __shared__ int scnt[16];
    const int tid = threadIdx.x;
    const int bid = blockIdx.x;
    const int h   = bid & 7;
    const int ct  = (bid >> 3) & 15;
    const int b   = bid >> 7;

    if (bid == 0 && tid == 0) g_fb_n = 0;   // whole grid finishes before select
    if (tid < 16) scnt[tid] = 0;
    __syncthreads();

    const int q  = tid & 3;                 // float4 within the 64B tile row
    const int sr = tid >> 2;                // 0..63
    const float4* __restrict__ x4 = reinterpret_cast<const float4*>(x);
    const size_t base = (size_t)b * SS * (CC / 4) + ct * 4 + q
                      + (size_t)(h * CHROWS + sr) * (CC / 4);
    const int colbase = b * CC + ct * 16 + q * 4;
    const int s0 = h * CHROWS + sr;

    for (int itb = 0; itb < 4; itb++) {
        // ---- front-batched loads (independent, no intervening branches) ----
        float4 v[4];
#pragma unroll
        for (int g = 0; g < 4; g++)
            v[g] = __ldcs(&x4[base + (size_t)((itb * 4 + g) * 64) * (CC / 4)]);

        // ---- filter/append tail ----
#pragma unroll
        for (int g = 0; g < 4; g++) {
            float m = fmaxf(fmaxf(v[g].x, v[g].y), fmaxf(v[g].z, v[g].w));
            if (m >= THRESH) {
                const int s = s0 + (itb * 4 + g) * 64;
                float vals[4] = {v[g].x, v[g].y, v[g].z, v[g].w};
#pragma unroll
                for (int l = 0; l < 4; l++) {
                    if (vals[l] >= THRESH) {
                        const int cl = q * 4 + l;
                        int pos = atomicAdd(&scnt[cl], 1);
                        if (pos < CHCAP) {
                            unsigned int key = __float_as_uint(vals[l]) | 0x80000000u;
                            g_cand[((size_t)(colbase + l) * CH + h) * CHCAP + pos] =
                                ((unsigned long long)key << 32) | (unsigned int)s;
                        }
                    }
                }
            }
        }
    }
    __syncthreads();
    if (tid < 16)
        g_cnt[(b * CC + ct * 16 + tid) * CH + h] = scnt[tid];
}

// ---------------------------------------------------------------------------
// Select kernel: one warp per column. Compact chunk segments into smem, then
// register bitonic sort (128-wide when n<=128, ~85% of columns; else 256),
// take top-64, bitonic re-sort by original index, write out.
// ---------------------------------------------------------------------------
__global__ void __launch_bounds__(256) select_kernel(float* __restrict__ out) {
    __shared__ unsigned long long sbuf[8][NSEL];    // 16 KB

    const int tid  = threadIdx.x;
    const int w    = tid >> 5;
    const int lane = tid & 31;
    const int col  = blockIdx.x * 8 + w;
    const int b    = col >> 8;
    const int c    = col & (CC - 1);

    // counts + exclusive scan over 8 chunks (lanes 0..7)
    int cnt = (lane < CH) ? g_cnt[col * CH + lane] : 0;
    unsigned int ovf = __ballot_sync(0xffffffffu, (lane < CH) && (cnt > CHCAP));
    int sc = cnt;
#pragma unroll
    for (int d = 1; d < 8; d <<= 1) {
        int t2 = __shfl_up_sync(0xffffffffu, sc, d);
        if (lane >= d) sc += t2;
    }
    const int n = __shfl_sync(0xffffffffu, sc, CH - 1);
    const int excl = sc - cnt;

    if (n >= KK && n <= NSEL && ovf == 0u) {
        // ---- compact segments into smem ----
#pragma unroll
        for (int h = 0; h < CH; h++) {
            int chn  = __shfl_sync(0xffffffffu, cnt, h);
            int bs   = __shfl_sync(0xffffffffu, excl, h);
            const unsigned long long* src = &g_cand[((size_t)col * CH + h) * CHCAP];
            for (int i = lane; i < chn; i += 32)
                sbuf[w][bs + i] = src[i];
        }
        __syncwarp();

        unsigned long long t6, t7;   // will hold elements [top-64) ascending

        if (n <= 128) {
            // ======== 128-wide path (R=4) ========
            unsigned long long v[4];
#pragma unroll
            for (int r = 0; r < 4; r++) {
                int e = r * 32 + lane;
                v[r] = (e < n) ? sbuf[w][e] : 0ull;
            }
#pragma unroll
            for (int k = 2; k <= 128; k <<= 1) {
#pragma unroll
                for (int j = k >> 1; j > 0; j >>= 1) {
                    if (j < 32) {
#pragma unroll
                        for (int r = 0; r < 4; r++) {
                            const int e = r * 32 + lane;
                            unsigned long long pv =
                                __shfl_xor_sync(0xffffffffu, v[r], j);
                            bool keep_min = (((e & k) == 0) == ((lane & j) == 0));
                            v[r] = ((v[r] < pv) == keep_min) ? v[r] : pv;
                        }
                    } else {
                        const int jr = j >> 5;
#pragma unroll
                        for (int r = 0; r < 4; r++) {
                            if ((r & jr) == 0) {
                                const int r2 = r | jr;
                                const int e = r * 32 + lane;
                                bool asc = ((e & k) == 0);
                                unsigned long long a = v[r], bb = v[r2];
                                if (asc ? (a > bb) : (a < bb)) { v[r] = bb; v[r2] = a; }
                            }
                        }
                    }
                }
            }
            t6 = v[2]; t7 = v[3];          // elements [64,128) = top 64
        } else {
            // ======== 256-wide path (R=8) ========
            unsigned long long v[8];
#pragma unroll
            for (int r = 0; r < 8; r++) {
                int e = r * 32 + lane;
                v[r] = (e < n) ? sbuf[w][e] : 0ull;
            }
#pragma unroll
            for (int k = 2; k <= 256; k <<= 1) {
#pragma unroll
                for (int j = k >> 1; j > 0; j >>= 1) {
                    if (j < 32) {
#pragma unroll
                        for (int r = 0; r < 8; r++) {
                            const int e = r * 32 + lane;
                            unsigned long long pv =
                                __shfl_xor_sync(0xffffffffu, v[r], j);
                            bool keep_min = (((e & k) == 0) == ((lane & j) == 0));
                            v[r] = ((v[r] < pv) == keep_min) ? v[r] : pv;
                        }
                    } else {
                        const int jr = j >> 5;
#pragma unroll
                        for (int r = 0; r < 8; r++) {
                            if ((r & jr) == 0) {
                                const int r2 = r | jr;
                                const int e = r * 32 + lane;
                                bool asc = ((e & k) == 0);
                                unsigned long long a = v[r], bb = v[r2];
                                if (asc ? (a > bb) : (a < bb)) { v[r] = bb; v[r2] = a; }
                            }
                        }
                    }
                }
            }
            t6 = v[6]; t7 = v[7];          // elements [192,256) = top 64
        }

        // ---- bitonic ascending sort of the 64 selected by low-32 (index s) ----
#pragma unroll
        for (int k = 2; k <= 64; k <<= 1) {
#pragma unroll
            for (int j = k >> 1; j > 0; j >>= 1) {
                if (j < 32) {
                    {
                        const int f = lane;                    // t6
                        unsigned long long pv = __shfl_xor_sync(0xffffffffu, t6, j);
                        bool keep_min = (((f & k) == 0) == ((lane & j) == 0));
                        bool mine_min = ((unsigned int)t6 < (unsigned int)pv);
                        t6 = (mine_min == keep_min) ? t6 : pv;
                    }
                    {
                        const int f = 32 + lane;               // t7
                        unsigned long long pv = __shfl_xor_sync(0xffffffffu, t7, j);
                        bool keep_min = (((f & k) == 0) == ((lane & j) == 0));
                        bool mine_min = ((unsigned int)t7 < (unsigned int)pv);
                        t7 = (mine_min == keep_min) ? t7 : pv;
                    }
                } else {  // j == 32 (k == 64): ascending merge across t6/t7
                    unsigned long long a = t6, bb = t7;
                    if ((unsigned int)a > (unsigned int)bb) { t6 = bb; t7 = a; }
                }
            }
        }

        // ---- write: element f -> out[b][f][c] ----
        {
            unsigned int k6 = (unsigned int)(t6 >> 32);
            unsigned int k7 = (unsigned int)(t7 >> 32);
            out[((size_t)b * KK + lane) * CC + c]        = __uint_as_float(k6 & 0x7FFFFFFFu);
            out[((size_t)b * KK + 32 + lane) * CC + c]   = __uint_as_float(k7 & 0x7FFFFFFFu);
        }
    } else {
        if (lane == 0) {
            unsigned int i = atomicAdd(&g_fb_n, 1u);
            g_fb_list[i] = col;
        }
    }
}

// ---------------------------------------------------------------------------
// Exact fallback (expected no-op): block per flagged column; smem-cached
// column, 64-pass bitwise select on (key,s) composite + ordered scatter.
// ---------------------------------------------------------------------------
__global__ void __launch_bounds__(256) fallback_kernel(const float* __restrict__ x,
                                                       float* __restrict__ out) {
    __shared__ float scol[SS];              // 32 KB
    __shared__ int scnt[256];
    const int tid = threadIdx.x;
    const unsigned int nfb = g_fb_n;

    for (unsigned int i = blockIdx.x; i < nfb; i += gridDim.x) {
        const int col = g_fb_list[i];
        const int b = col >> 8;
        const int c = col & (CC - 1);

        for (int s = tid; s < SS; s += 256)
            scol[s] = x[((size_t)b * SS + s) * CC + c];
        __syncthreads();

        unsigned long long V = 0;
        for (int bit = 63; bit >= 0; bit--) {
            unsigned long long cand = V | (1ull << bit);
            int local = 0;
            for (int s = tid; s < SS; s += 256) {
                unsigned long long comp =
                    ((unsigned long long)fkey(scol[s]) << 32) | (unsigned int)s;
                local += (comp >= cand);
            }
            scnt[tid] = local;
            __syncthreads();
            for (int st = 128; st > 0; st >>= 1) {
                if (tid < st) scnt[tid] += scnt[tid + st];
                __syncthreads();
            }
            int cntv = scnt[0];
            __syncthreads();
            if (cntv >= KK) V = cand;
        }

        const int per = SS / 256;
        int lcnt = 0;
        for (int k2 = 0; k2 < per; k2++) {
            int s = tid * per + k2;
            unsigned long long comp =
                ((unsigned long long)fkey(scol[s]) << 32) | (unsigned int)s;
            lcnt += (comp >= V);
        }
        scnt[tid] = lcnt;
        __syncthreads();
        for (int off = 1; off < 256; off <<= 1) {
            int vv = scnt[tid];
            int ww = (tid >= off) ? scnt[tid - off] : 0;
            __syncthreads();
            scnt[tid] = vv + ww;
            __syncthreads();
        }
        int base = scnt[tid] - lcnt;
        for (int k2 = 0; k2 < per; k2++) {
            int s = tid * per + k2;
            unsigned long long comp =
                ((unsigned long long)fkey(scol[s]) << 32) | (unsigned int)s;
            if (comp >= V) {
                if (base < KK)
                    out[((size_t)b * KK + base) * CC + c] = scol[s];
                base++;
            }
        }
        __syncthreads();
    }
}

extern "C" void kernel_launch(void* const* d_in, const int* in_sizes, int n_in,
                              void* d_out, int out_size) {
    const float* x = (const float*)d_in[0];
    float* out = (float*)d_out;

    stream_kernel<<<BB * 16 * CH, 256>>>(x);     // 4096 blocks
    select_kernel<<<NCOL / 8, 256>>>(out);       // 1024 blocks
    fallback_kernel<<<64, 256>>>(x, out);
}

// round 9
// speedup vs baseline: 3.1158x; 1.0080x over previous
#include <cuda_runtime.h>
#include <cuda_bf16.h>
#include <stdint.h>

// Problem constants (fixed by setup_inputs)
#define BB    32
#define SS    8192
#define CC    256
#define KK    64
#define NCOL  (BB * CC)      // 8192 columns
#define TILE  16             // columns per block
#define CAP   256            // candidate slots per column (mean 117, sd 10.7; 13-sigma)

// Threshold 2.1875: P(X>t)=0.0143 -> ~117 candidates/column.
#define THRESH 2.1875f

// Fallback plumbing (device globals — allocation-free per harness rules)
__device__ unsigned int g_fb_n;
__device__ int          g_fb_list[NCOL];

__device__ __forceinline__ unsigned int fkey(float f) {
    unsigned int u = __float_as_uint(f);
    return (u & 0x80000000u) ? ~u : (u | 0x80000000u);
}

// ---------------------------------------------------------------------------
// Fused kernel: block = (b, 16-column tile), 512 threads.
// Phase 1: stream all 8192 rows coalesced with explicit 4-deep load batching,
//          filter into per-column smem candidate buffers (shared atomics).
// Phase 2: warp w selects top-64 of column w via register bitonic sort,
//          re-sorts by original index, writes out. No global scratch.
// ---------------------------------------------------------------------------
__global__ void __launch_bounds__(512) fused_kernel(const float* __restrict__ x,
                                                    float* __restrict__ out) {
    __shared__ unsigned long long sbuf[TILE][CAP];   // 32 KB
    __shared__ int scnt[TILE];

    const int tid = threadIdx.x;
    const int ct  = blockIdx.x & 15;        // column tile
    const int b   = blockIdx.x >> 4;        // batch

    if (tid < TILE) scnt[tid] = 0;
    __syncthreads();

    // ---- phase 1: stream ----
    const int q  = tid & 3;                 // float4 within the 16-col chunk
    const int sr = tid >> 2;                // 0..127
    const float4* __restrict__ x4 = reinterpret_cast<const float4*>(x);
    const size_t base = (size_t)b * SS * (CC / 4) + ct * 4 + q
                      + (size_t)sr * (CC / 4);

    for (int itb = 0; itb < 16; itb++) {
        // front-batched independent loads (MLP = 4/thread)
        float4 v[4];
#pragma unroll
        for (int g = 0; g < 4; g++)
            v[g] = __ldcs(&x4[base + (size_t)((itb * 4 + g) * 128) * (CC / 4)]);

        // filter/append tail
#pragma unroll
        for (int g = 0; g < 4; g++) {
            float m = fmaxf(fmaxf(v[g].x, v[g].y), fmaxf(v[g].z, v[g].w));
            if (m >= THRESH) {
                const int s = sr + (itb * 4 + g) * 128;
                float vals[4] = {v[g].x, v[g].y, v[g].z, v[g].w};
#pragma unroll
                for (int l = 0; l < 4; l++) {
                    if (vals[l] >= THRESH) {
                        const int cl = q * 4 + l;
                        int pos = atomicAdd(&scnt[cl], 1);
                        if (pos < CAP) {
                            unsigned int key = __float_as_uint(vals[l]) | 0x80000000u;
                            sbuf[cl][pos] =
                                ((unsigned long long)key << 32) | (unsigned int)s;
                        }
                    }
                }
            }
        }
    }
    __syncthreads();

    // ---- phase 2: warp w selects column w ----
    const int w    = tid >> 5;
    const int lane = tid & 31;
    const int n    = scnt[w];
    const int c    = ct * TILE + w;         // global column within C

    if (n >= KK && n <= CAP) {
        unsigned long long t6, t7;          // will hold the top-64 ascending

        if (n <= 128) {
            // ======== 128-wide bitonic (R=4), ~85% of columns ========
            unsigned long long v[4];
#pragma unroll
            for (int r = 0; r < 4; r++) {
                int e = r * 32 + lane;
                v[r] = (e < n) ? sbuf[w][e] : 0ull;   // zeros sink to bottom
            }
#pragma unroll
            for (int k = 2; k <= 128; k <<= 1) {
#pragma unroll
                for (int j = k >> 1; j > 0; j >>= 1) {
                    if (j < 32) {
#pragma unroll
                        for (int r = 0; r < 4; r++) {
                            const int e = r * 32 + lane;
                            unsigned long long pv =
                                __shfl_xor_sync(0xffffffffu, v[r], j);
                            bool keep_min = (((e & k) == 0) == ((lane & j) == 0));
                            v[r] = ((v[r] < pv) == keep_min) ? v[r] : pv;
                        }
                    } else {
                        const int jr = j >> 5;
#pragma unroll
                        for (int r = 0; r < 4; r++) {
                            if ((r & jr) == 0) {
                                const int r2 = r | jr;
                                const int e = r * 32 + lane;
                                bool asc = ((e & k) == 0);
                                unsigned long long a = v[r], bb = v[r2];
                                if (asc ? (a > bb) : (a < bb)) { v[r] = bb; v[r2] = a; }
                            }
                        }
                    }
                }
            }
            t6 = v[2]; t7 = v[3];           // elements [64,128) = top 64
        } else {
            // ======== 256-wide bitonic (R=8) ========
            unsigned long long v[8];
#pragma unroll
            for (int r = 0; r < 8; r++) {
                int e = r * 32 + lane;
                v[r] = (e < n) ? sbuf[w][e] : 0ull;
            }
#pragma unroll
            for (int k = 2; k <= 256; k <<= 1) {
#pragma unroll
                for (int j = k >> 1; j > 0; j >>= 1) {
                    if (j < 32) {
#pragma unroll
                        for (int r = 0; r < 8; r++) {
                            const int e = r * 32 + lane;
                            unsigned long long pv =
                                __shfl_xor_sync(0xffffffffu, v[r], j);
                            bool keep_min = (((e & k) == 0) == ((lane & j) == 0));
                            v[r] = ((v[r] < pv) == keep_min) ? v[r] : pv;
                        }
                    } else {
                        const int jr = j >> 5;
#pragma unroll
                        for (int r = 0; r < 8; r++) {
                            if ((r & jr) == 0) {
                                const int r2 = r | jr;
                                const int e = r * 32 + lane;
                                bool asc = ((e & k) == 0);
                                unsigned long long a = v[r], bb = v[r2];
                                if (asc ? (a > bb) : (a < bb)) { v[r] = bb; v[r2] = a; }
                            }
                        }
                    }
                }
            }
            t6 = v[6]; t7 = v[7];           // elements [192,256) = top 64
        }

        // ---- bitonic ascending sort of the 64 selected by low-32 (index s) ----
#pragma unroll
        for (int k = 2; k <= 64; k <<= 1) {
#pragma unroll
            for (int j = k >> 1; j > 0; j >>= 1) {
                if (j < 32) {
                    {
                        const int f = lane;                    // t6
                        unsigned long long pv = __shfl_xor_sync(0xffffffffu, t6, j);
                        bool keep_min = (((f & k) == 0) == ((lane & j) == 0));
                        bool mine_min = ((unsigned int)t6 < (unsigned int)pv);
                        t6 = (mine_min == keep_min) ? t6 : pv;
                    }
                    {
                        const int f = 32 + lane;               // t7
                        unsigned long long pv = __shfl_xor_sync(0xffffffffu, t7, j);
                        bool keep_min = (((f & k) == 0) == ((lane & j) == 0));
                        bool mine_min = ((unsigned int)t7 < (unsigned int)pv);
                        t7 = (mine_min == keep_min) ? t7 : pv;
                    }
                } else {  // j == 32 (k == 64): ascending merge across t6/t7
                    unsigned long long a = t6, bb = t7;
                    if ((unsigned int)a > (unsigned int)bb) { t6 = bb; t7 = a; }
                }
            }
        }

        // ---- write: element f -> out[b][f][c] ----
        unsigned int k6 = (unsigned int)(t6 >> 32);
        unsigned int k7 = (unsigned int)(t7 >> 32);
        out[((size_t)b * KK + lane) * CC + c]      = __uint_as_float(k6 & 0x7FFFFFFFu);
        out[((size_t)b * KK + 32 + lane) * CC + c] = __uint_as_float(k7 & 0x7FFFFFFFu);
    } else {
        if (lane == 0) {
            unsigned int i = atomicAdd(&g_fb_n, 1u);
            g_fb_list[i] = b * CC + c;
        }
    }
}

// ---------------------------------------------------------------------------
// Exact fallback (expected no-op): block per flagged column; smem-cached
// column, 64-pass bitwise select on (key,s) composite + ordered scatter.
// ---------------------------------------------------------------------------
__global__ void __launch_bounds__(256) fallback_kernel(const float* __restrict__ x,
                                                       float* __restrict__ out) {
    __shared__ float scol[SS];              // 32 KB
    __shared__ int scnt[256];
    const int tid = threadIdx.x;
    const unsigned int nfb = g_fb_n;

    for (unsigned int i = blockIdx.x; i < nfb; i += gridDim.x) {
        const int col = g_fb_list[i];
        const int b = col >> 8;
        const int c = col & (CC - 1);

        for (int s = tid; s < SS; s += 256)
            scol[s] = x[((size_t)b * SS + s) * CC + c];
        __syncthreads();

        unsigned long long V = 0;
        for (int bit = 63; bit >= 0; bit--) {
            unsigned long long cand = V | (1ull << bit);
            int local = 0;
            for (int s = tid; s < SS; s += 256) {
                unsigned long long comp =
                    ((unsigned long long)fkey(scol[s]) << 32) | (unsigned int)s;
                local += (comp >= cand);
            }
            scnt[tid] = local;
            __syncthreads();
            for (int st = 128; st > 0; st >>= 1) {
                if (tid < st) scnt[tid] += scnt[tid + st];
                __syncthreads();
            }
            int cntv = scnt[0];
            __syncthreads();
            if (cntv >= KK) V = cand;
        }

        const int per = SS / 256;
        int lcnt = 0;
        for (int k2 = 0; k2 < per; k2++) {
            int s = tid * per + k2;
            unsigned long long comp =
                ((unsigned long long)fkey(scol[s]) << 32) | (unsigned int)s;
            lcnt += (comp >= V);
        }
        scnt[tid] = lcnt;
        __syncthreads();
        for (int off = 1; off < 256; off <<= 1) {
            int vv = scnt[tid];
            int ww = (tid >= off) ? scnt[tid - off] : 0;
            __syncthreads();
            scnt[tid] = vv + ww;
            __syncthreads();
        }
        int base = scnt[tid] - lcnt;
        for (int k2 = 0; k2 < per; k2++) {
            int s = tid * per + k2;
            unsigned long long comp =
                ((unsigned long long)fkey(scol[s]) << 32) | (unsigned int)s;
            if (comp >= V) {
                if (base < KK)
                    out[((size_t)b * KK + base) * CC + c] = scol[s];
                base++;
            }
        }
        __syncthreads();
    }
}

extern "C" void kernel_launch(void* const* d_in, const int* in_sizes, int n_in,
                              void* d_out, int out_size) {
    const float* x = (const float*)d_in[0];
    float* out = (float*)d_out;

    void* fb_ptr = nullptr;
    cudaGetSymbolAddress(&fb_ptr, g_fb_n);
    cudaMemsetAsync(fb_ptr, 0, sizeof(unsigned int));

    fused_kernel<<<BB * (CC / TILE), 512>>>(x, out);   // 512 blocks
    fallback_kernel<<<64, 256>>>(x, out);
}